// round 16
// baseline (speedup 1.0000x reference)
#include <cuda_runtime.h>

// SceneEngine: closed-form subset-sum factorization.
//   Σ over non-empty subsets of exp(Σ_s exist[s,bit_s]) = Π_s(e0+e1) − Π_s e0
//   number_prob  -> elementary symmetric polynomial DP on Π_s(e0 + t·e1)
//   attr prob[d] -> (Π_s(e0 + e1·exp(a[s,d])) − Π_s e0) / Z
//
// R15: R12's fine role split × R14's single-wave layout.
// 128 blocks × 448 threads = 14 warps/block (two 7-warp role sets, one per b).
// Attr warps cover 8 pairs, lane=(k<<2)|(h<<1)|g: h splits dims, g splits
// slots (s 0-4 / 5-8); partial products combine via shfl-mul, dim halves via
// shfl-add. Per-lane chain <= ~30 loads / ~35 exps. Barrier-free, direct GMEM.
//   per b: r0: exist_prob (h=1) + symmetric DP + number (h=0)
//          r1/r2: type k0-7 / k8-15   r3/r4: size   r5/r6: color

constexpr int NS = 9;

constexpr int OFF_EXIST  = 0;
constexpr int OFF_NUM    = 73728;
constexpr int OFF_TYPE   = 110592;
constexpr int OFF_NTYPE  = 135168;
constexpr int OFF_RTYPE  = 145408;
constexpr int OFF_SIZE   = 145664;
constexpr int OFF_NSIZE  = 174336;
constexpr int OFF_RSIZE  = 186624;
constexpr int OFF_COLOR  = 186880;
constexpr int OFF_NCOLOR = 231936;
constexpr int OFF_RCOLOR = 252416;

__device__ __forceinline__ float warp_min(float v)
{
#pragma unroll
    for (int off = 16; off >= 1; off >>= 1)
        v = fminf(v, __shfl_xor_sync(0xFFFFFFFFu, v, off));
    return v;
}

// attr role with slot+dim split. Warp covers 8 pairs (k = kbase + lane>>2).
// lane bits: h = (lane>>1)&1 selects dims [0,H0) or [H0,D);
//            g = lane&1 selects slots s in [0,5) or [5,9).
// LOWK warps (k = 0..7) also write norm and rule.
template <int D, int H0, int MAXND, bool LOWK>
__device__ __forceinline__ void attr_sg(
    const float* __restrict__ attr,
    const float* __restrict__ exist,
    int b, int kbase, int lane,
    float* __restrict__ out,
    int off_prob, int off_norm, int off_rule)
{
    int k    = (lane >> 2) + kbase;
    int h    = (lane >> 1) & 1;
    int g    = lane & 1;
    int pair = b * 16 + k;
    int nd    = h ? (D - H0) : H0;
    int dbase = h ? H0 : 0;
    int s0    = g ? 5 : 0;
    int ns    = g ? 4 : 5;

    // ---- partial products over this lane's slot range ----
    const float2* __restrict__ er =
        (const float2*)(exist + (size_t)pair * 18 + 2 * s0);
    const float* __restrict__ a =
        attr + (size_t)pair * NS * D + s0 * D + dbase;

    float pp[MAXND];
#pragma unroll
    for (int j = 0; j < MAXND; j++) pp[j] = 1.0f;
    float pS0 = 1.0f, pZp = 1.0f;

#pragma unroll
    for (int s = 0; s < 5; s++) {
        if (s < ns) {
            float2 e = er[s];
            float e0 = __expf(e.x);
            float e1 = __expf(e.y);
            pS0 *= e0;
            pZp *= (e0 + e1);
#pragma unroll
            for (int j = 0; j < MAXND; j++) {
                if (j < nd)
                    pp[j] *= fmaf(e1, __expf(a[s * D + j]), e0);
            }
        }
    }

    // ---- combine slot halves (xor 1): products multiply ----
    float S0 = pS0 * __shfl_xor_sync(0xFFFFFFFFu, pS0, 1);
    float Zp = pZp * __shfl_xor_sync(0xFFFFFFFFu, pZp, 1);
    float p[MAXND];
#pragma unroll
    for (int j = 0; j < MAXND; j++)
        p[j] = pp[j] * __shfl_xor_sync(0xFFFFFFFFu, pp[j], 1);

    float invZ = __fdividef(1.0f, Zp - S0);
    float part = 0.0f;
#pragma unroll
    for (int j = 0; j < MAXND; j++) {
        if (j < nd) {
            p[j] = (p[j] - S0) * invZ;
            part += p[j];
        }
    }
    // ---- combine dim halves (xor 2): sums add ----
    float sum = part + __shfl_xor_sync(0xFFFFFFFFu, part, 2);
    float nic = fminf(sum, 1.0f);

    if (g == 0) {
        float* __restrict__ op = out + off_prob + (size_t)pair * (D + 1) + dbase;
#pragma unroll
        for (int j = 0; j < MAXND; j++)
            if (j < nd) op[j] = p[j];
        if (h) op[nd] = 1.0f - nic;      // element D (dbase + nd == D)

        if (LOWK) {
            float inv = __fdividef(1.0f, sum);
            float* __restrict__ on = out + off_norm + (size_t)(b * 8 + k) * D + dbase;
#pragma unroll
            for (int j = 0; j < MAXND; j++)
                if (j < nd) on[j] = p[j] * inv;
        }
    }

    if (LOWK) {
        float v = warp_min(nic);         // min over the warp's 8 k's (= k<8)
        if (lane == 0) out[off_rule + b] = v;
    }
}

__global__ __launch_bounds__(448, 1)
void scene_engine_kernel(const float* __restrict__ exist,
                         const float* __restrict__ typ,
                         const float* __restrict__ siz,
                         const float* __restrict__ col,
                         float* __restrict__ out)
{
    int t = threadIdx.x;
    int w = t >> 5;
    int lane = t & 31;
    int b = blockIdx.x * 2 + (w >= 7 ? 1 : 0);   // two b's per block
    int role = (w >= 7) ? (w - 7) : w;

    if (role == 0) {
        // lane = (p<<1)|h : h=1 writes exist_prob, h=0 does DP + number.
        int p = lane >> 1;
        int h = lane & 1;
        int pair = b * 16 + p;

        const float2* __restrict__ er = (const float2*)(exist + (size_t)pair * 18);
        float e0[NS], e1[NS];
#pragma unroll
        for (int s = 0; s < NS; s++) {
            float2 e = er[s];
            e0[s] = __expf(e.x);
            e1[s] = __expf(e.y);
        }

        if (h) {
            float2* __restrict__ oex = (float2*)(out + OFF_EXIST + (size_t)pair * 18);
#pragma unroll
            for (int s = 0; s < NS; s++)
                oex[s] = make_float2(e0[s], e1[s]);
        } else {
            // elementary symmetric polynomial DP
            float c[NS + 1];
            c[0] = 1.0f;
#pragma unroll
            for (int i = 1; i <= NS; i++) c[i] = 0.0f;
#pragma unroll
            for (int s = 0; s < NS; s++) {
#pragma unroll
                for (int j = NS; j >= 1; j--)
                    c[j] = fmaf(c[j], e0[s], c[j - 1] * e1[s]);
                c[0] *= e0[s];
            }
            float Z = 0.0f;
#pragma unroll
            for (int j = 1; j <= NS; j++) Z += c[j];
            float invZ = __fdividef(1.0f, Z);

            float* __restrict__ onum = out + OFF_NUM + (size_t)pair * NS;
#pragma unroll
            for (int n = 0; n < NS; n++) onum[n] = c[n + 1] * invZ;
        }
    } else if (role == 1) {
        attr_sg<5, 3, 3, true >(typ, exist, b, 0, lane, out, OFF_TYPE, OFF_NTYPE, OFF_RTYPE);
    } else if (role == 2) {
        attr_sg<5, 3, 3, false>(typ, exist, b, 8, lane, out, OFF_TYPE, OFF_NTYPE, OFF_RTYPE);
    } else if (role == 3) {
        attr_sg<6, 3, 3, true >(siz, exist, b, 0, lane, out, OFF_SIZE, OFF_NSIZE, OFF_RSIZE);
    } else if (role == 4) {
        attr_sg<6, 3, 3, false>(siz, exist, b, 8, lane, out, OFF_SIZE, OFF_NSIZE, OFF_RSIZE);
    } else if (role == 5) {
        attr_sg<10, 5, 5, true >(col, exist, b, 0, lane, out, OFF_COLOR, OFF_NCOLOR, OFF_RCOLOR);
    } else {
        attr_sg<10, 5, 5, false>(col, exist, b, 8, lane, out, OFF_COLOR, OFF_NCOLOR, OFF_RCOLOR);
    }
}

extern "C" void kernel_launch(void* const* d_in, const int* in_sizes, int n_in,
                              void* d_out, int out_size)
{
    const float* exist = (const float*)d_in[0];
    const float* typ   = (const float*)d_in[1];
    const float* siz   = (const float*)d_in[2];
    const float* col   = (const float*)d_in[3];
    float* out = (float*)d_out;

    // 128 blocks × 448 threads: single wave, 14 role warps/block (2 b's).
    scene_engine_kernel<<<128, 448>>>(exist, typ, siz, col, out);
}